// round 1
// baseline (speedup 1.0000x reference)
#include <cuda_runtime.h>
#include <math_constants.h>

#define L 1096
#define SD 384

__device__ __forceinline__ int ridf(int i) {
    return (i >= 1) + (i >= 401) + (i >= 801) + (i >= 816) +
           (i >= 936) + (i >= 956) + (i >= 1076);
}

__device__ __forceinline__ int pidf(int i, int j, int ri, int rj) {
    if (ri == 0 || rj == 0) return (ri == 0 && rj == 0) ? 0 : 1;
    if (ri == 1 && rj == 1) { int d = abs(i - j); return d == 1 ? 2 : (d > 1 ? 3 : 0); }
    if (ri == 1 || rj == 1) return 4;
    if (ri == rj) return ri + 3;  // 5 + (ri-2)
    int a = min(ri, rj) - 2, b = max(ri, rj) - 2;
    int p = 11 + a * 5 - (a * (a - 1)) / 2 + (b - a - 1);
    return p > 31 ? 31 : p;
}

__global__ __launch_bounds__(256) void cae_kernel(
    const float* __restrict__ hd,   const float* __restrict__ mask,
    const float* __restrict__ mhc,  const float* __restrict__ pep,
    const float* __restrict__ lv,   const float* __restrict__ lj,
    const float* __restrict__ hv,   const float* __restrict__ hj,
    const float* __restrict__ seq_W, const float* __restrict__ seq_b,
    const float* __restrict__ pos_W, const float* __restrict__ pos_b,
    const float* __restrict__ tab1, const float* __restrict__ b1,
    const float* __restrict__ tab2, const float* __restrict__ b2,
    const float* __restrict__ ctok, const float* __restrict__ cw,
    const float* __restrict__ region_w,
    float* __restrict__ out)
{
    __shared__ float zvec[32 * 128];
    __shared__ float feat[21];
    __shared__ float sc[64];

    int tid = threadIdx.x;
    int row = blockIdx.x;

    // Build the 32-entry z table in smem: zvec[pid] = [tab1[pid>>2]+b1, tab2[pid&3]+b2]
    for (int e = tid; e < 32 * 128; e += 256) {
        int pid = e >> 7, c = e & 127;
        float v = (c < 64) ? (tab1[(pid >> 2) * 64 + c] + b1[c])
                           : (tab2[(pid & 3) * 64 + (c - 64)] + b2[c - 64]);
        zvec[e] = v;
    }

    // Region of this row
    int reg, start;
    const float* x = nullptr;
    if      (row == 0)    { reg = 0; start = 0; }
    else if (row < 401)   { reg = 1; start = 1;    x = hd;  }
    else if (row < 801)   { reg = 2; start = 401;  x = mhc; }
    else if (row < 816)   { reg = 3; start = 801;  x = pep; }
    else if (row < 936)   { reg = 4; start = 816;  x = lv;  }
    else if (row < 956)   { reg = 5; start = 936;  x = lj;  }
    else if (row < 1076)  { reg = 6; start = 956;  x = hv;  }
    else                  { reg = 7; start = 1076; x = hj;  }
    int r = row - start;

    if (reg >= 1 && tid < 21) feat[tid] = x[r * 21 + tid];
    if (reg >= 2 && tid < 32) {
        // one_d: ang_k = idx * pi / MAX_LEN^(2k/64); idx == local arange == r
        float freq = CUDART_PI_F / powf(2056.0f, (2.0f * (float)tid) / 64.0f);
        float a = (float)r * freq;
        sc[tid]      = sinf(a);
        sc[tid + 32] = cosf(a);
    }
    __syncthreads();

    // ---- s_out row ----
    if (reg == 0) {
        float w = cw[0];
        for (int c = tid; c < SD; c += 256) out[c] = w * ctok[c];
    } else {
        float fm = (reg == 1) ? mask[r] : 0.0f;
        float w0 = 1.0f, w1 = 0.0f;
        if (reg >= 2) { w0 = region_w[(reg - 2) * 2 + 0]; w1 = region_w[(reg - 2) * 2 + 1]; }
        for (int c = tid; c < SD; c += 256) {
            float acc = seq_b[c] + fm * seq_W[c];
            #pragma unroll
            for (int k = 0; k < 21; k++) acc += feat[k] * seq_W[(k + 1) * SD + c];
            if (reg >= 2) {
                float p = pos_b[c];
                #pragma unroll
                for (int k = 0; k < 64; k++) p += sc[k] * pos_W[k * SD + c];
                acc = w0 * acc + w1 * p;
            }
            out[(size_t)row * SD + c] = acc;
        }
    }

    // ---- z row-slab: z[row][j][0:128] for all j ----
    float* z = out + (size_t)L * SD + (size_t)row * L * 128;
    int ri = ridf(row);
    int warp = tid >> 5, lane = tid & 31;
    const float4* zv4 = (const float4*)zvec;
    float4* z4 = (float4*)z;
    for (int j = warp; j < L; j += 8) {
        int pid = pidf(row, j, ri, ridf(j));
        z4[(size_t)j * 32 + lane] = zv4[pid * 32 + lane];
    }
}

extern "C" void kernel_launch(void* const* d_in, const int* in_sizes, int n_in,
                              void* d_out, int out_size) {
    // Two plausible input orders (setup-dict vs reference-signature); they differ
    // only in where `mask` sits. Disambiguate: in_sizes[2]==400 -> signature order
    // (hd, mask, hd_idx, mhc, ...); in_sizes[2]==8400 -> dict order
    // (hd, hd_idx, mhc, mhc_idx, ...).
    const float *hd, *mask, *mhc, *pep, *lv, *lj, *hv, *hj;
    if (in_sizes[2] == 400) {  // signature order
        hd   = (const float*)d_in[0];
        mask = (const float*)d_in[1];
        mhc  = (const float*)d_in[3];
        pep  = (const float*)d_in[5];
        lv   = (const float*)d_in[7];
        lj   = (const float*)d_in[9];
        hv   = (const float*)d_in[11];
        hj   = (const float*)d_in[13];
    } else {                   // dict order
        hd   = (const float*)d_in[0];
        mhc  = (const float*)d_in[2];
        pep  = (const float*)d_in[4];
        lv   = (const float*)d_in[6];
        lj   = (const float*)d_in[8];
        hv   = (const float*)d_in[10];
        hj   = (const float*)d_in[12];
        mask = (const float*)d_in[14];
    }
    // Indices 15..25 coincide in both orders.
    const float* seq_W = (const float*)d_in[15];
    const float* seq_b = (const float*)d_in[16];
    const float* pos_W = (const float*)d_in[17];
    const float* pos_b = (const float*)d_in[18];
    const float* tab1  = (const float*)d_in[19];
    const float* b1    = (const float*)d_in[20];
    const float* tab2  = (const float*)d_in[21];
    const float* b2    = (const float*)d_in[22];
    const float* ctok  = (const float*)d_in[23];
    const float* cw    = (const float*)d_in[24];
    const float* rw    = (const float*)d_in[25];

    float* out = (float*)d_out;
    cae_kernel<<<L, 256>>>(hd, mask, mhc, pep, lv, lj, hv, hj,
                           seq_W, seq_b, pos_W, pos_b,
                           tab1, b1, tab2, b2, ctok, cw, rw, out);
}

// round 2
// speedup vs baseline: 1.1855x; 1.1855x over previous
#include <cuda_runtime.h>
#include <math_constants.h>

#define L 1096
#define SD 384

__device__ __forceinline__ int pidf(int i, int j, int ri, int rj) {
    if (ri == 0 || rj == 0) return (ri == 0 && rj == 0) ? 0 : 1;
    if (ri == 1 && rj == 1) { int d = abs(i - j); return d == 1 ? 2 : (d > 1 ? 3 : 0); }
    if (ri == 1 || rj == 1) return 4;
    if (ri == rj) return ri + 3;  // 5 + (ri-2)
    int a = min(ri, rj) - 2, b = max(ri, rj) - 2;
    int p = 11 + a * 5 - (a * (a - 1)) / 2 + (b - a - 1);
    return p > 31 ? 31 : p;
}

__global__ __launch_bounds__(256) void cae_kernel(
    const float* __restrict__ hd,   const float* __restrict__ mask,
    const float* __restrict__ mhc,  const float* __restrict__ pep,
    const float* __restrict__ lv,   const float* __restrict__ lj,
    const float* __restrict__ hv,   const float* __restrict__ hj,
    const float* __restrict__ seq_W, const float* __restrict__ seq_b,
    const float* __restrict__ pos_W, const float* __restrict__ pos_b,
    const float* __restrict__ tab1, const float* __restrict__ b1,
    const float* __restrict__ tab2, const float* __restrict__ b2,
    const float* __restrict__ ctok, const float* __restrict__ cw,
    const float* __restrict__ region_w,
    float* __restrict__ out)
{
    __shared__ float feat[21];
    __shared__ float sc[64];

    const int tid  = threadIdx.x;
    const int row  = blockIdx.x;
    const int lane = tid & 31;

    // Per-thread bias slice for z vectors (lane 0-15 -> b1, 16-31 -> b2)
    float4 bias4 = (lane < 16) ? ((const float4*)b1)[lane]
                               : ((const float4*)b2)[lane - 16];

    // Region of this row
    int reg, start;
    const float* x = nullptr;
    if      (row == 0)    { reg = 0; start = 0; }
    else if (row < 401)   { reg = 1; start = 1;    x = hd;  }
    else if (row < 801)   { reg = 2; start = 401;  x = mhc; }
    else if (row < 816)   { reg = 3; start = 801;  x = pep; }
    else if (row < 936)   { reg = 4; start = 816;  x = lv;  }
    else if (row < 956)   { reg = 5; start = 936;  x = lj;  }
    else if (row < 1076)  { reg = 6; start = 956;  x = hv;  }
    else                  { reg = 7; start = 1076; x = hj;  }
    const int r = row - start;

    if (reg >= 1 && tid < 21) feat[tid] = x[r * 21 + tid];
    if (reg >= 2 && tid < 32) {
        // one_d: ang_k = idx * pi / MAX_LEN^(2k/64); idx == local arange == r
        float freq = CUDART_PI_F / powf(2056.0f, (2.0f * (float)tid) / 64.0f);
        float a = (float)r * freq;
        sc[tid]      = sinf(a);
        sc[tid + 32] = cosf(a);
    }
    __syncthreads();

    // ---- s_out row ----
    if (reg == 0) {
        float w = cw[0];
        for (int c = tid; c < SD; c += 256) out[c] = w * ctok[c];
    } else {
        float fm = (reg == 1) ? mask[r] : 0.0f;
        float w0 = 1.0f, w1 = 0.0f;
        if (reg >= 2) { w0 = region_w[(reg - 2) * 2 + 0]; w1 = region_w[(reg - 2) * 2 + 1]; }
        for (int c = tid; c < SD; c += 256) {
            float acc = seq_b[c] + fm * seq_W[c];
            #pragma unroll
            for (int k = 0; k < 21; k++) acc += feat[k] * seq_W[(k + 1) * SD + c];
            if (reg >= 2) {
                float p = pos_b[c];
                #pragma unroll
                for (int k = 0; k < 64; k++) p += sc[k] * pos_W[k * SD + c];
                acc = w0 * acc + w1 * p;
            }
            out[(size_t)row * SD + c] = acc;
        }
    }

    // ---- z row-slab: z[row][j][0:128] streamed by pid-constant segments ----
    float4* z4 = (float4*)(out + (size_t)L * SD) + (size_t)row * (L * 32);
    const int ri = reg;

    auto seg = [&](int jlo, int jhi, int pid) {
        if (jlo >= jhi) return;
        float4 t = (lane < 16) ? ((const float4*)tab1)[(pid >> 2) * 16 + lane]
                               : ((const float4*)tab2)[(pid & 3) * 16 + (lane - 16)];
        float4 v = make_float4(t.x + bias4.x, t.y + bias4.y,
                               t.z + bias4.z, t.w + bias4.w);
        float4* dst = z4 + (size_t)jlo * 32;
        const int n4 = (jhi - jlo) * 32;
        #pragma unroll 4
        for (int idx = tid; idx < n4; idx += 256) {
            asm volatile("st.global.cs.v4.f32 [%0], {%1,%2,%3,%4};"
                         :: "l"(dst + idx), "f"(v.x), "f"(v.y), "f"(v.z), "f"(v.w)
                         : "memory");
        }
    };

    const int starts[9] = {0, 1, 401, 801, 816, 936, 956, 1076, 1096};
    #pragma unroll
    for (int rj = 0; rj < 8; rj++) {
        const int js = starts[rj], je = starts[rj + 1];
        if (ri == 1 && rj == 1) {
            // hd x hd band: split around the diagonal
            int i = row;
            seg(1, min(i - 1, 401), 3);
            seg(max(i - 1, 1), min(i, 401), 2);
            seg(i, i + 1, 0);
            seg(min(i + 1, 401), min(i + 2, 401), 2);
            seg(min(i + 2, 401), 401, 3);
        } else {
            seg(js, je, pidf(row, js, ri, rj));
        }
    }
}

extern "C" void kernel_launch(void* const* d_in, const int* in_sizes, int n_in,
                              void* d_out, int out_size) {
    const float *hd, *mask, *mhc, *pep, *lv, *lj, *hv, *hj;
    if (in_sizes[2] == 400) {  // signature order (hd, mask, hd_idx, mhc, ...)
        hd   = (const float*)d_in[0];
        mask = (const float*)d_in[1];
        mhc  = (const float*)d_in[3];
        pep  = (const float*)d_in[5];
        lv   = (const float*)d_in[7];
        lj   = (const float*)d_in[9];
        hv   = (const float*)d_in[11];
        hj   = (const float*)d_in[13];
    } else {                   // dict order (hd, hd_idx, mhc, mhc_idx, ..., mask, ...)
        hd   = (const float*)d_in[0];
        mhc  = (const float*)d_in[2];
        pep  = (const float*)d_in[4];
        lv   = (const float*)d_in[6];
        lj   = (const float*)d_in[8];
        hv   = (const float*)d_in[10];
        hj   = (const float*)d_in[12];
        mask = (const float*)d_in[14];
    }
    const float* seq_W = (const float*)d_in[15];
    const float* seq_b = (const float*)d_in[16];
    const float* pos_W = (const float*)d_in[17];
    const float* pos_b = (const float*)d_in[18];
    const float* tab1  = (const float*)d_in[19];
    const float* b1    = (const float*)d_in[20];
    const float* tab2  = (const float*)d_in[21];
    const float* b2    = (const float*)d_in[22];
    const float* ctok  = (const float*)d_in[23];
    const float* cw    = (const float*)d_in[24];
    const float* rw    = (const float*)d_in[25];

    float* out = (float*)d_out;
    cae_kernel<<<L, 256>>>(hd, mask, mhc, pep, lv, lj, hv, hj,
                           seq_W, seq_b, pos_W, pos_b,
                           tab1, b1, tab2, b2, ctok, cw, rw, out);
}